// round 3
// baseline (speedup 1.0000x reference)
#include <cuda_runtime.h>
#include <cuda_bf16.h>
#include <stdint.h>

// ============================================================================
// Problem constants
// ============================================================================
#define MROWS 4096              // IN_DIM
#define KDIM  2048              // H
#define NDIM  2048              // H
#define NPTS  2097152
#define UGRID 64

// GEMM tiling
#define BM 128
#define BN 128
#define BK 32
#define NCHUNK (KDIM / BK)      // 64
#define STAGES 3
#define GEMM_THREADS 256
#define NTILES_N (NDIM / BN)    // 16

// SMEM: 4 planes per stage (A_hi, A_lo, B_hi, B_lo), each 128 rows x 80 bytes
#define ROW_BYTES 80            // 32 bf16 = 64B + 16B pad (conflict-free ldmatrix)
#define PLANE_BYTES (128 * ROW_BYTES)          // 10240
#define STAGE_BYTES (4 * PLANE_BYTES)          // 40960
#define GEMM_SMEM (STAGES * STAGE_BYTES)       // 122880
#define PL_A_HI 0
#define PL_A_LO (1 * PLANE_BYTES)
#define PL_B_HI (2 * PLANE_BYTES)
#define PL_B_LO (3 * PLANE_BYTES)

// ============================================================================
// Scratch (static __device__ — no allocations allowed)
// ============================================================================
__device__ __nv_bfloat16 g_h1_hi[(size_t)MROWS * KDIM];
__device__ __nv_bfloat16 g_h1_lo[(size_t)MROWS * KDIM];
__device__ __nv_bfloat16 g_w2t_hi[(size_t)NDIM * KDIM];
__device__ __nv_bfloat16 g_w2t_lo[(size_t)NDIM * KDIM];
__device__ float         g_upart[NTILES_N * MROWS];   // per-n-tile partial sums
__device__ float         g_u[UGRID * UGRID];

// ============================================================================
// PTX helpers (arch-neutral: ldmatrix / mma.sync / cp.async only)
// ============================================================================
__device__ __forceinline__ uint32_t smem_to_u32(const void* p) {
    uint32_t r;
    asm("{ .reg .u64 t; cvta.to.shared.u64 t, %1; cvt.u32.u64 %0, t; }"
        : "=r"(r) : "l"(p));
    return r;
}

__device__ __forceinline__ void cp_async16(uint32_t saddr, const void* gaddr) {
    asm volatile("cp.async.cg.shared.global [%0], [%1], 16;"
                 :: "r"(saddr), "l"(gaddr));
}
#define CP_ASYNC_COMMIT() asm volatile("cp.async.commit_group;" ::: "memory")
#define CP_ASYNC_WAIT(n)  asm volatile("cp.async.wait_group %0;" :: "n"(n) : "memory")

__device__ __forceinline__ void ldsm_x4(uint32_t* r, uint32_t addr) {
    asm volatile("ldmatrix.sync.aligned.m8n8.x4.shared.b16 {%0,%1,%2,%3}, [%4];"
                 : "=r"(r[0]), "=r"(r[1]), "=r"(r[2]), "=r"(r[3]) : "r"(addr));
}

__device__ __forceinline__ void mma_bf16(float* c, const uint32_t* a,
                                         const uint32_t* b) {
    asm volatile(
        "mma.sync.aligned.m16n8k16.row.col.f32.bf16.bf16.f32 "
        "{%0,%1,%2,%3}, {%4,%5,%6,%7}, {%8,%9}, {%0,%1,%2,%3};"
        : "+f"(c[0]), "+f"(c[1]), "+f"(c[2]), "+f"(c[3])
        : "r"(a[0]), "r"(a[1]), "r"(a[2]), "r"(a[3]), "r"(b[0]), "r"(b[1]));
}

// ============================================================================
// Kernel 1: h1 = tanh(W1 + b1), split into bf16 hi/lo planes
// ============================================================================
__global__ void prep_h1_kernel(const float* __restrict__ W1,
                               const float* __restrict__ b1) {
    int i4 = blockIdx.x * blockDim.x + threadIdx.x;
    if (i4 >= (MROWS * KDIM) / 4) return;
    float4 w = reinterpret_cast<const float4*>(W1)[i4];
    int col = (i4 * 4) & (KDIM - 1);
    float v0 = tanhf(w.x + b1[col + 0]);
    float v1 = tanhf(w.y + b1[col + 1]);
    float v2 = tanhf(w.z + b1[col + 2]);
    float v3 = tanhf(w.w + b1[col + 3]);
    __nv_bfloat16 h0 = __float2bfloat16(v0);
    __nv_bfloat16 h1 = __float2bfloat16(v1);
    __nv_bfloat16 h2 = __float2bfloat16(v2);
    __nv_bfloat16 h3 = __float2bfloat16(v3);
    __nv_bfloat16 l0 = __float2bfloat16(v0 - __bfloat162float(h0));
    __nv_bfloat16 l1 = __float2bfloat16(v1 - __bfloat162float(h1));
    __nv_bfloat16 l2 = __float2bfloat16(v2 - __bfloat162float(h2));
    __nv_bfloat16 l3 = __float2bfloat16(v3 - __bfloat162float(h3));
    __nv_bfloat162* hip = reinterpret_cast<__nv_bfloat162*>(g_h1_hi) + i4 * 2;
    __nv_bfloat162* lop = reinterpret_cast<__nv_bfloat162*>(g_h1_lo) + i4 * 2;
    hip[0] = __nv_bfloat162(h0, h1);
    hip[1] = __nv_bfloat162(h2, h3);
    lop[0] = __nv_bfloat162(l0, l1);
    lop[1] = __nv_bfloat162(l2, l3);
}

// ============================================================================
// Kernel 2: W2T[n][k] = W2[k][n], split into bf16 hi/lo (tiled transpose)
// ============================================================================
__global__ void prep_w2_kernel(const float* __restrict__ W2) {
    __shared__ float tile[32][33];
    int bx = blockIdx.x, by = blockIdx.y;
    int tx = threadIdx.x, ty = threadIdx.y;   // (32, 8)
    #pragma unroll
    for (int r = 0; r < 32; r += 8)
        tile[ty + r][tx] = W2[(size_t)(by * 32 + ty + r) * NDIM + bx * 32 + tx];
    __syncthreads();
    #pragma unroll
    for (int r = 0; r < 32; r += 8) {
        float v = tile[tx][ty + r];
        int n = bx * 32 + ty + r;
        int k = by * 32 + tx;
        __nv_bfloat16 hi = __float2bfloat16(v);
        __nv_bfloat16 lo = __float2bfloat16(v - __bfloat162float(hi));
        size_t o = (size_t)n * KDIM + k;
        g_w2t_hi[o] = hi;
        g_w2t_lo[o] = lo;
    }
}

// ============================================================================
// Kernel 3: bf16x3 HMMA GEMM (fp32 accuracy) + tanh + fused @W3 reduction.
//   C tile = 128x128; 8 warps laid out 2(M) x 4(N), each warp 64x32.
//   Epilogue: per-row sum of tanh(acc + b2[n]) * W3[n] -> g_upart[ntile][m].
// ============================================================================
__global__ void __launch_bounds__(GEMM_THREADS, 1)
gemm_kernel(const float* __restrict__ b2, const float* __restrict__ W3) {
    extern __shared__ char smem[];
    const uint32_t sbase = smem_to_u32(smem);
    const int tid  = threadIdx.x;
    const int lane = tid & 31;
    const int wid  = tid >> 5;
    const int warp_m = wid >> 2;          // 0..1
    const int warp_n = wid & 3;           // 0..3

    const int ntile = blockIdx.x;         // 0..15
    const int mbase = blockIdx.y * BM;
    const int nbase = ntile * BN;

    // global sources for the 4 planes (row-major [row][K])
    const __nv_bfloat16* gsrc[4];
    gsrc[0] = g_h1_hi  + (size_t)mbase * KDIM;
    gsrc[1] = g_h1_lo  + (size_t)mbase * KDIM;
    gsrc[2] = g_w2t_hi + (size_t)nbase * KDIM;
    gsrc[3] = g_w2t_lo + (size_t)nbase * KDIM;

    // per-thread load coordinates: 2 iters x 4 planes, idx -> (row, 16B chunk)
    const int l_row0 = tid >> 2;          // idx = tid      -> rows 0..63
    const int l_row1 = (256 + tid) >> 2;  // idx = 256+tid  -> rows 64..127
    const int l_ch   = tid & 3;

    // ldmatrix lane offsets (bytes within a plane)
    const uint32_t frag_row = (lane & 7) + 8 * ((lane >> 3) & 1);
    const uint32_t frag_col16 = (lane >> 4) * 16;   // +8 cols for mats 2,3
    const uint32_t a_lane = (warp_m * 64 + frag_row) * ROW_BYTES + frag_col16;
    const uint32_t b_lane = (warp_n * 32 + frag_row) * ROW_BYTES + frag_col16;

    float acc[4][4][4];
    #pragma unroll
    for (int i = 0; i < 4; i++)
        #pragma unroll
        for (int j = 0; j < 4; j++)
            #pragma unroll
            for (int r = 0; r < 4; r++) acc[i][j][r] = 0.0f;

    // ---- async load of one chunk into stage s ----
    auto load_chunk = [&](int c, int s) {
        const uint32_t st = sbase + s * STAGE_BYTES;
        const int kb = c * BK;
        #pragma unroll
        for (int p = 0; p < 4; p++) {
            const __nv_bfloat16* src = gsrc[p] + kb + l_ch * 8;
            uint32_t dst = st + p * PLANE_BYTES + l_ch * 16;
            cp_async16(dst + l_row0 * ROW_BYTES, src + (size_t)l_row0 * KDIM);
            cp_async16(dst + l_row1 * ROW_BYTES, src + (size_t)l_row1 * KDIM);
        }
        CP_ASYNC_COMMIT();
    };

    // prologue: fill pipeline
    load_chunk(0, 0);
    load_chunk(1, 1);
    load_chunk(2, 2);

    for (int c = 0; c < NCHUNK; c++) {
        CP_ASYNC_WAIT(STAGES - 1);
        __syncthreads();
        const uint32_t st = sbase + (c % STAGES) * STAGE_BYTES;

        #pragma unroll
        for (int kk = 0; kk < 2; kk++) {          // two k16 steps per chunk
            const uint32_t koff = kk * 32;        // 16 bf16 = 32 bytes
            uint32_t ahi[4][4], alo[4][4];
            uint32_t bhi[4][2], blo[4][2];
            #pragma unroll
            for (int mf = 0; mf < 4; mf++) {
                uint32_t off = mf * (16 * ROW_BYTES) + koff + a_lane;
                ldsm_x4(ahi[mf], st + PL_A_HI + off);
                ldsm_x4(alo[mf], st + PL_A_LO + off);
            }
            #pragma unroll
            for (int q = 0; q < 2; q++) {
                uint32_t off = q * (16 * ROW_BYTES) + koff + b_lane;
                uint32_t r[4];
                ldsm_x4(r, st + PL_B_HI + off);
                bhi[2*q][0] = r[0]; bhi[2*q+1][0] = r[1];
                bhi[2*q][1] = r[2]; bhi[2*q+1][1] = r[3];
                ldsm_x4(r, st + PL_B_LO + off);
                blo[2*q][0] = r[0]; blo[2*q+1][0] = r[1];
                blo[2*q][1] = r[2]; blo[2*q+1][1] = r[3];
            }
            #pragma unroll
            for (int mf = 0; mf < 4; mf++)
                #pragma unroll
                for (int nf = 0; nf < 4; nf++)
                    mma_bf16(acc[mf][nf], ahi[mf], bhi[nf]);
            #pragma unroll
            for (int mf = 0; mf < 4; mf++)
                #pragma unroll
                for (int nf = 0; nf < 4; nf++)
                    mma_bf16(acc[mf][nf], ahi[mf], blo[nf]);
            #pragma unroll
            for (int mf = 0; mf < 4; mf++)
                #pragma unroll
                for (int nf = 0; nf < 4; nf++)
                    mma_bf16(acc[mf][nf], alo[mf], bhi[nf]);
        }
        __syncthreads();
        if (c + STAGES < NCHUNK) load_chunk(c + STAGES, (c + STAGES) % STAGES);
    }

    // ---- epilogue: tanh(+b2) * W3, reduce to per-row partials ----
    __syncthreads();                    // done with smem stages; reuse below
    float* red = reinterpret_cast<float*>(smem);   // [4 warps_n][128 rows]

    const int g = lane >> 2;
    const int t = lane & 3;
    float p0[4], p1[4];
    #pragma unroll
    for (int mf = 0; mf < 4; mf++) { p0[mf] = 0.0f; p1[mf] = 0.0f; }

    #pragma unroll
    for (int nf = 0; nf < 4; nf++) {
        const int col = nbase + warp_n * 32 + nf * 8 + 2 * t;
        const float w30 = W3[col], w31 = W3[col + 1];
        const float b20 = b2[col], b21 = b2[col + 1];
        #pragma unroll
        for (int mf = 0; mf < 4; mf++) {
            p0[mf] += tanhf(acc[mf][nf][0] + b20) * w30
                    + tanhf(acc[mf][nf][1] + b21) * w31;
            p1[mf] += tanhf(acc[mf][nf][2] + b20) * w30
                    + tanhf(acc[mf][nf][3] + b21) * w31;
        }
    }
    // reduce over the quad (4 lanes covering the 8 columns of each row)
    #pragma unroll
    for (int mf = 0; mf < 4; mf++) {
        p0[mf] += __shfl_xor_sync(0xffffffffu, p0[mf], 1);
        p0[mf] += __shfl_xor_sync(0xffffffffu, p0[mf], 2);
        p1[mf] += __shfl_xor_sync(0xffffffffu, p1[mf], 1);
        p1[mf] += __shfl_xor_sync(0xffffffffu, p1[mf], 2);
    }
    if (t == 0) {
        #pragma unroll
        for (int mf = 0; mf < 4; mf++) {
            int row = warp_m * 64 + mf * 16 + g;
            red[warp_n * 128 + row]     = p0[mf];
            red[warp_n * 128 + row + 8] = p1[mf];
        }
    }
    __syncthreads();
    if (tid < 128) {
        float s = red[tid] + red[128 + tid] + red[256 + tid] + red[384 + tid];
        g_upart[ntile * MROWS + mbase + tid] = s;
    }
}

// ============================================================================
// Kernel 4: u[m] = 3 * tanh(b3 + sum over n-tiles of partials)
// ============================================================================
__global__ void finish_u_kernel(const float* __restrict__ b3) {
    int m = blockIdx.x * blockDim.x + threadIdx.x;
    if (m >= MROWS) return;
    float s = 0.0f;
    #pragma unroll
    for (int j = 0; j < NTILES_N; j++) s += g_upart[j * MROWS + m];
    g_u[m] = 3.0f * tanhf(s + b3[0]);
}

// ============================================================================
// Kernel 5: quadratic B-spline evaluation over u (64x64), 2M points
// ============================================================================
__global__ void spline_kernel(const float* __restrict__ points,
                              float* __restrict__ out) {
    __shared__ float su[UGRID * UGRID];
    for (int i = threadIdx.x; i < UGRID * UGRID; i += blockDim.x)
        su[i] = g_u[i];
    __syncthreads();

    for (int n = blockIdx.x * blockDim.x + threadIdx.x; n < NPTS;
         n += gridDim.x * blockDim.x) {
        float2 pt = reinterpret_cast<const float2*>(points)[n];
        float xc = (pt.x + 1.0f) * 0.5f;
        float yc = pt.y;
        float px = xc * 62.0f;
        float py = yc * 62.0f;
        float fx = floorf(px), fy = floorf(py);
        float tx = px - fx,   ty = py - fy;
        int posx = min((int)fx + 1, 62);
        int posy = min((int)fy + 1, 62);
        float bx0 = 0.5f * (1.0f - tx) * (1.0f - tx);
        float bx1 = -tx * tx + tx + 0.5f;
        float bx2 = 0.5f * tx * tx;
        float by0 = 0.5f * (1.0f - ty) * (1.0f - ty);
        float by1 = -ty * ty + ty + 0.5f;
        float by2 = 0.5f * ty * ty;
        const float* row0 = su + (posx - 1) * UGRID + (posy - 1);
        const float* row1 = row0 + UGRID;
        const float* row2 = row1 + UGRID;
        float r0 = row0[0] * by0 + row0[1] * by1 + row0[2] * by2;
        float r1 = row1[0] * by0 + row1[1] * by1 + row1[2] * by2;
        float r2 = row2[0] * by0 + row2[1] * by1 + row2[2] * by2;
        out[n] = r0 * bx0 + r1 * bx1 + r2 * bx2;
    }
}

// ============================================================================
// kernel_launch
// ============================================================================
extern "C" void kernel_launch(void* const* d_in, const int* in_sizes, int n_in,
                              void* d_out, int out_size) {
    const float* points = (const float*)d_in[0];
    const float* W1     = (const float*)d_in[1];
    const float* b1     = (const float*)d_in[2];
    const float* W2     = (const float*)d_in[3];
    const float* b2     = (const float*)d_in[4];
    const float* W3     = (const float*)d_in[5];
    const float* b3     = (const float*)d_in[6];
    float* out = (float*)d_out;

    static bool attr_done = false;
    if (!attr_done) {
        cudaFuncSetAttribute(gemm_kernel,
                             cudaFuncAttributeMaxDynamicSharedMemorySize,
                             GEMM_SMEM);
        attr_done = true;
    }

    prep_h1_kernel<<<(MROWS * KDIM / 4) / 256, 256>>>(W1, b1);
    prep_w2_kernel<<<dim3(NDIM / 32, KDIM / 32), dim3(32, 8)>>>(W2);
    gemm_kernel<<<dim3(NTILES_N, MROWS / BM), GEMM_THREADS, GEMM_SMEM>>>(b2, W3);
    finish_u_kernel<<<MROWS / 256, 256>>>(b3);
    spline_kernel<<<1184, 256>>>(points, out);
}

// round 5
// speedup vs baseline: 1.3465x; 1.3465x over previous
#include <cuda_runtime.h>
#include <cuda_fp16.h>
#include <stdint.h>

// ============================================================================
// Problem constants
// ============================================================================
#define MROWS 4096              // IN_DIM
#define KDIM  2048              // H
#define NDIM  2048              // H
#define NPTS  2097152
#define UGRID 64

// GEMM tiling
#define BM 128
#define BN 128
#define BK 32
#define NCHUNK (KDIM / BK)      // 64
#define STAGES 4
#define GEMM_THREADS 256
#define NTILES_N (NDIM / BN)    // 16

// SMEM: 3 planes per stage (A_hi, A_lo, B), each 128 rows x 80 bytes
#define ROW_BYTES 80            // 32 fp16 = 64B + 16B pad (conflict-free ldmatrix)
#define PLANE_BYTES (128 * ROW_BYTES)          // 10240
#define STAGE_BYTES (3 * PLANE_BYTES)          // 30720
#define GEMM_SMEM (STAGES * STAGE_BYTES)       // 122880
#define PL_A_HI 0
#define PL_A_LO (1 * PLANE_BYTES)
#define PL_B    (2 * PLANE_BYTES)

// ============================================================================
// Scratch (static __device__ — no allocations allowed)
// ============================================================================
__device__ __half g_h1_hi[(size_t)MROWS * KDIM];
__device__ __half g_h1_lo[(size_t)MROWS * KDIM];
__device__ __half g_w2t[(size_t)NDIM * KDIM];
__device__ float  g_upart[NTILES_N * MROWS];   // per-n-tile partial sums
__device__ float  g_u[UGRID * UGRID];

// ============================================================================
// PTX helpers (arch-neutral: ldmatrix / mma.sync / cp.async only)
// ============================================================================
__device__ __forceinline__ uint32_t smem_to_u32(const void* p) {
    uint32_t r;
    asm("{ .reg .u64 t; cvta.to.shared.u64 t, %1; cvt.u32.u64 %0, t; }"
        : "=r"(r) : "l"(p));
    return r;
}

__device__ __forceinline__ void cp_async16(uint32_t saddr, const void* gaddr) {
    asm volatile("cp.async.cg.shared.global [%0], [%1], 16;"
                 :: "r"(saddr), "l"(gaddr));
}
#define CP_ASYNC_COMMIT() asm volatile("cp.async.commit_group;" ::: "memory")
#define CP_ASYNC_WAIT(n)  asm volatile("cp.async.wait_group %0;" :: "n"(n) : "memory")

__device__ __forceinline__ void ldsm_x4(uint32_t* r, uint32_t addr) {
    asm volatile("ldmatrix.sync.aligned.m8n8.x4.shared.b16 {%0,%1,%2,%3}, [%4];"
                 : "=r"(r[0]), "=r"(r[1]), "=r"(r[2]), "=r"(r[3]) : "r"(addr));
}

__device__ __forceinline__ void mma_f16(float* c, const uint32_t* a,
                                        const uint32_t* b) {
    asm volatile(
        "mma.sync.aligned.m16n8k16.row.col.f32.f16.f16.f32 "
        "{%0,%1,%2,%3}, {%4,%5,%6,%7}, {%8,%9}, {%0,%1,%2,%3};"
        : "+f"(c[0]), "+f"(c[1]), "+f"(c[2]), "+f"(c[3])
        : "r"(a[0]), "r"(a[1]), "r"(a[2]), "r"(a[3]), "r"(b[0]), "r"(b[1]));
}

// ============================================================================
// Kernel 1: h1 = tanh(W1 + b1), split into fp16 hi/lo planes (exact split;
//           lo residual lands in subnormals — fine, its error is ~a*2e-6)
// ============================================================================
__global__ void prep_h1_kernel(const float* __restrict__ W1,
                               const float* __restrict__ b1) {
    int i4 = blockIdx.x * blockDim.x + threadIdx.x;
    if (i4 >= (MROWS * KDIM) / 4) return;
    float4 w = reinterpret_cast<const float4*>(W1)[i4];
    int col = (i4 * 4) & (KDIM - 1);
    float v0 = tanhf(w.x + b1[col + 0]);
    float v1 = tanhf(w.y + b1[col + 1]);
    float v2 = tanhf(w.z + b1[col + 2]);
    float v3 = tanhf(w.w + b1[col + 3]);
    __half h0 = __float2half(v0);
    __half h1 = __float2half(v1);
    __half h2 = __float2half(v2);
    __half h3 = __float2half(v3);
    __half l0 = __float2half(v0 - __half2float(h0));
    __half l1 = __float2half(v1 - __half2float(h1));
    __half l2 = __float2half(v2 - __half2float(h2));
    __half l3 = __float2half(v3 - __half2float(h3));
    __half2* hip = reinterpret_cast<__half2*>(g_h1_hi) + i4 * 2;
    __half2* lop = reinterpret_cast<__half2*>(g_h1_lo) + i4 * 2;
    hip[0] = __half2(h0, h1);
    hip[1] = __half2(h2, h3);
    lop[0] = __half2(l0, l1);
    lop[1] = __half2(l2, l3);
}

// ============================================================================
// Kernel 2: W2T[n][k] = fp16(W2[k][n])  (tiled transpose, single plane)
// ============================================================================
__global__ void prep_w2_kernel(const float* __restrict__ W2) {
    __shared__ float tile[32][33];
    int bx = blockIdx.x, by = blockIdx.y;
    int tx = threadIdx.x, ty = threadIdx.y;   // (32, 8)
    #pragma unroll
    for (int r = 0; r < 32; r += 8)
        tile[ty + r][tx] = W2[(size_t)(by * 32 + ty + r) * NDIM + bx * 32 + tx];
    __syncthreads();
    #pragma unroll
    for (int r = 0; r < 32; r += 8) {
        float v = tile[tx][ty + r];
        int n = bx * 32 + ty + r;
        int k = by * 32 + tx;
        g_w2t[(size_t)n * KDIM + k] = __float2half(v);
    }
}

// ============================================================================
// Kernel 3: fp16x2-split HMMA GEMM + tanh + fused @W3 reduction.
//   C tile = 128x128; 8 warps laid out 2(M) x 4(N), each warp 64x32.
//   acc += Ahi*B + Alo*B  (B single fp16; dominant err = B rounding 2^-12)
//   Epilogue: per-row sum of tanh(acc + b2[n]) * W3[n] -> g_upart[ntile][m].
// ============================================================================
__global__ void __launch_bounds__(GEMM_THREADS, 1)
gemm_kernel(const float* __restrict__ b2, const float* __restrict__ W3) {
    extern __shared__ char smem[];
    const uint32_t sbase = smem_to_u32(smem);
    const int tid  = threadIdx.x;
    const int lane = tid & 31;
    const int wid  = tid >> 5;
    const int warp_m = wid >> 2;          // 0..1
    const int warp_n = wid & 3;           // 0..3

    const int ntile = blockIdx.x;         // 0..15
    const int mbase = blockIdx.y * BM;
    const int nbase = ntile * BN;

    // global sources for the 3 planes (row-major [row][K])
    const __half* gsrc[3];
    gsrc[0] = g_h1_hi + (size_t)mbase * KDIM;
    gsrc[1] = g_h1_lo + (size_t)mbase * KDIM;
    gsrc[2] = g_w2t   + (size_t)nbase * KDIM;

    // per-thread load coordinates: 2 iters x 3 planes, idx -> (row, 16B chunk)
    const int l_row0 = tid >> 2;          // rows 0..63
    const int l_row1 = (256 + tid) >> 2;  // rows 64..127
    const int l_ch   = tid & 3;

    // ldmatrix lane offsets (bytes within a plane)
    const uint32_t frag_row = (lane & 7) + 8 * ((lane >> 3) & 1);
    const uint32_t frag_col16 = (lane >> 4) * 16;
    const uint32_t a_lane = (warp_m * 64 + frag_row) * ROW_BYTES + frag_col16;
    const uint32_t b_lane = (warp_n * 32 + frag_row) * ROW_BYTES + frag_col16;

    float acc[4][4][4];
    #pragma unroll
    for (int i = 0; i < 4; i++)
        #pragma unroll
        for (int j = 0; j < 4; j++)
            #pragma unroll
            for (int r = 0; r < 4; r++) acc[i][j][r] = 0.0f;

    // ---- async load of one chunk into stage s ----
    auto load_chunk = [&](int c, int s) {
        const uint32_t st = sbase + s * STAGE_BYTES;
        const int kb = c * BK;
        #pragma unroll
        for (int p = 0; p < 3; p++) {
            const __half* src = gsrc[p] + kb + l_ch * 8;
            uint32_t dst = st + p * PLANE_BYTES + l_ch * 16;
            cp_async16(dst + l_row0 * ROW_BYTES, src + (size_t)l_row0 * KDIM);
            cp_async16(dst + l_row1 * ROW_BYTES, src + (size_t)l_row1 * KDIM);
        }
        CP_ASYNC_COMMIT();
    };

    // prologue: fill pipeline with STAGES-1 chunks
    #pragma unroll
    for (int c = 0; c < STAGES - 1; c++) load_chunk(c, c);

    for (int c = 0; c < NCHUNK; c++) {
        CP_ASYNC_WAIT(STAGES - 2);
        __syncthreads();
        // issue next loads first (overwrites the stage all warps just finished)
        if (c + STAGES - 1 < NCHUNK)
            load_chunk(c + STAGES - 1, (c + STAGES - 1) % STAGES);

        const uint32_t st = sbase + (c % STAGES) * STAGE_BYTES;

        #pragma unroll
        for (int kk = 0; kk < 2; kk++) {          // two k16 steps per chunk
            const uint32_t koff = kk * 32;        // 16 fp16 = 32 bytes
            uint32_t ahi[4][4], alo[4][4], bf[4][2];
            #pragma unroll
            for (int mf = 0; mf < 4; mf++) {
                uint32_t off = mf * (16 * ROW_BYTES) + koff + a_lane;
                ldsm_x4(ahi[mf], st + PL_A_HI + off);
                ldsm_x4(alo[mf], st + PL_A_LO + off);
            }
            #pragma unroll
            for (int q = 0; q < 2; q++) {
                uint32_t off = q * (16 * ROW_BYTES) + koff + b_lane;
                uint32_t r[4];
                ldsm_x4(r, st + PL_B + off);
                bf[2*q][0] = r[0]; bf[2*q+1][0] = r[1];
                bf[2*q][1] = r[2]; bf[2*q+1][1] = r[3];
            }
            #pragma unroll
            for (int mf = 0; mf < 4; mf++)
                #pragma unroll
                for (int nf = 0; nf < 4; nf++)
                    mma_f16(acc[mf][nf], ahi[mf], bf[nf]);
            #pragma unroll
            for (int mf = 0; mf < 4; mf++)
                #pragma unroll
                for (int nf = 0; nf < 4; nf++)
                    mma_f16(acc[mf][nf], alo[mf], bf[nf]);
        }
        __syncthreads();
    }

    // ---- epilogue: tanh(+b2) * W3, reduce to per-row partials ----
    float* red = reinterpret_cast<float*>(smem);   // [4 warps_n][128 rows]

    const int g = lane >> 2;
    const int t = lane & 3;
    float p0[4], p1[4];
    #pragma unroll
    for (int mf = 0; mf < 4; mf++) { p0[mf] = 0.0f; p1[mf] = 0.0f; }

    #pragma unroll
    for (int nf = 0; nf < 4; nf++) {
        const int col = nbase + warp_n * 32 + nf * 8 + 2 * t;
        const float w30 = W3[col], w31 = W3[col + 1];
        const float b20 = b2[col], b21 = b2[col + 1];
        #pragma unroll
        for (int mf = 0; mf < 4; mf++) {
            p0[mf] += tanhf(acc[mf][nf][0] + b20) * w30
                    + tanhf(acc[mf][nf][1] + b21) * w31;
            p1[mf] += tanhf(acc[mf][nf][2] + b20) * w30
                    + tanhf(acc[mf][nf][3] + b21) * w31;
        }
    }
    #pragma unroll
    for (int mf = 0; mf < 4; mf++) {
        p0[mf] += __shfl_xor_sync(0xffffffffu, p0[mf], 1);
        p0[mf] += __shfl_xor_sync(0xffffffffu, p0[mf], 2);
        p1[mf] += __shfl_xor_sync(0xffffffffu, p1[mf], 1);
        p1[mf] += __shfl_xor_sync(0xffffffffu, p1[mf], 2);
    }
    if (t == 0) {
        #pragma unroll
        for (int mf = 0; mf < 4; mf++) {
            int row = warp_m * 64 + mf * 16 + g;
            red[warp_n * 128 + row]     = p0[mf];
            red[warp_n * 128 + row + 8] = p1[mf];
        }
    }
    __syncthreads();
    if (tid < 128) {
        float s = red[tid] + red[128 + tid] + red[256 + tid] + red[384 + tid];
        g_upart[ntile * MROWS + mbase + tid] = s;
    }
}

// ============================================================================
// Kernel 4: u[m] = 3 * tanh(b3 + sum over n-tiles of partials)
// ============================================================================
__global__ void finish_u_kernel(const float* __restrict__ b3) {
    int m = blockIdx.x * blockDim.x + threadIdx.x;
    if (m >= MROWS) return;
    float s = 0.0f;
    #pragma unroll
    for (int j = 0; j < NTILES_N; j++) s += g_upart[j * MROWS + m];
    g_u[m] = 3.0f * tanhf(s + b3[0]);
}

// ============================================================================
// Kernel 5: quadratic B-spline evaluation over u (64x64), 2M points
// ============================================================================
__global__ void spline_kernel(const float* __restrict__ points,
                              float* __restrict__ out) {
    __shared__ float su[UGRID * UGRID];
    for (int i = threadIdx.x; i < UGRID * UGRID; i += blockDim.x)
        su[i] = g_u[i];
    __syncthreads();

    for (int n = blockIdx.x * blockDim.x + threadIdx.x; n < NPTS;
         n += gridDim.x * blockDim.x) {
        float2 pt = reinterpret_cast<const float2*>(points)[n];
        float xc = (pt.x + 1.0f) * 0.5f;
        float yc = pt.y;
        float px = xc * 62.0f;
        float py = yc * 62.0f;
        float fx = floorf(px), fy = floorf(py);
        float tx = px - fx,   ty = py - fy;
        int posx = min((int)fx + 1, 62);
        int posy = min((int)fy + 1, 62);
        float bx0 = 0.5f * (1.0f - tx) * (1.0f - tx);
        float bx1 = -tx * tx + tx + 0.5f;
        float bx2 = 0.5f * tx * tx;
        float by0 = 0.5f * (1.0f - ty) * (1.0f - ty);
        float by1 = -ty * ty + ty + 0.5f;
        float by2 = 0.5f * ty * ty;
        const float* row0 = su + (posx - 1) * UGRID + (posy - 1);
        const float* row1 = row0 + UGRID;
        const float* row2 = row1 + UGRID;
        float r0 = row0[0] * by0 + row0[1] * by1 + row0[2] * by2;
        float r1 = row1[0] * by0 + row1[1] * by1 + row1[2] * by2;
        float r2 = row2[0] * by0 + row2[1] * by1 + row2[2] * by2;
        out[n] = r0 * bx0 + r1 * bx1 + r2 * bx2;
    }
}

// ============================================================================
// kernel_launch
// ============================================================================
extern "C" void kernel_launch(void* const* d_in, const int* in_sizes, int n_in,
                              void* d_out, int out_size) {
    const float* points = (const float*)d_in[0];
    const float* W1     = (const float*)d_in[1];
    const float* b1     = (const float*)d_in[2];
    const float* W2     = (const float*)d_in[3];
    const float* b2     = (const float*)d_in[4];
    const float* W3     = (const float*)d_in[5];
    const float* b3     = (const float*)d_in[6];
    float* out = (float*)d_out;

    static bool attr_done = false;
    if (!attr_done) {
        cudaFuncSetAttribute(gemm_kernel,
                             cudaFuncAttributeMaxDynamicSharedMemorySize,
                             GEMM_SMEM);
        attr_done = true;
    }

    prep_h1_kernel<<<(MROWS * KDIM / 4) / 256, 256>>>(W1, b1);
    prep_w2_kernel<<<dim3(NDIM / 32, KDIM / 32), dim3(32, 8)>>>(W2);
    gemm_kernel<<<dim3(NTILES_N, MROWS / BM), GEMM_THREADS, GEMM_SMEM>>>(b2, W3);
    finish_u_kernel<<<MROWS / 256, 256>>>(b3);
    spline_kernel<<<1184, 256>>>(points, out);
}